// round 9
// baseline (speedup 1.0000x reference)
#include <cuda_runtime.h>
#include <math.h>

#define NELEM 16384
#define NB    16384
#define NBLK  64
#define NTHR  256
#define CAP   16
#define EAGER 4

typedef unsigned long long ull;

// Parity-double-buffered / monotone scratch: no cleanup pass.
__device__ float    g_bsum[2][NB];     // histogram (atomicAdd) — exact bucket sums
__device__ unsigned g_cnt[2][NB];      // bucket slot counts (atomicAdd)
__device__ float4   g_slot[NB * CAP];  // (time, exp, event, 0) — plain stores (R6-proven)
__device__ float    g_chunk[NBLK];     // per-chunk totals (read after full barrier)
__device__ float2   g_bpart[NBLK];     // per-block (num, den)
__device__ ull      g_done;            // monotone ticket; epoch = g_done >> 6
__device__ int      g_barcnt;          // gbar counter (self-resetting)
__device__ int      g_sense;           // gbar sense flag

static __device__ __forceinline__ ull ldv64(const ull* p) {
    ull v; asm volatile("ld.global.cg.u64 %0, [%1];" : "=l"(v) : "l"(p)); return v;
}
static __device__ __forceinline__ unsigned ldv32(const unsigned* p) {
    unsigned v; asm volatile("ld.global.cg.u32 %0, [%1];" : "=r"(v) : "l"(p)); return v;
}
static __device__ __forceinline__ float ldvf(const float* p) {
    float v; asm volatile("ld.global.cg.f32 %0, [%1];" : "=f"(v) : "l"(p)); return v;
}

static __device__ __forceinline__ int bucket_of(float t) {
    int b = (int)(t * 16384.0f);
    return b < 0 ? 0 : (b > NB - 1 ? NB - 1 : b);
}

// R6's proven sense-reversing grid barrier, verbatim (per-thread fence at entry).
__device__ __forceinline__ void gbar() {
    __threadfence();
    __syncthreads();
    if (threadIdx.x == 0) {
        volatile int* vs = &g_sense;
        int s = *vs;
        if (atomicAdd(&g_barcnt, 1) == NBLK - 1) {
            g_barcnt = 0;
            __threadfence();
            *vs = s ^ 1;
        } else {
            while (*vs == s) { }
        }
        __threadfence();
    }
    __syncthreads();
}

__global__ void __launch_bounds__(NTHR, 1) cox_kernel(
    const float* __restrict__ risk,
    const float* __restrict__ time,
    const float* __restrict__ event,
    float* __restrict__ out)
{
    const int t   = threadIdx.x;
    const int blk = blockIdx.x;
    const int i   = blk * NTHR + t;

    __shared__ unsigned sh_ep1;
    __shared__ float s_w[8];
    __shared__ float s_hi[2];
    __shared__ float rn[8], rd[8];

    // ---- Front: epoch via thread-0 broadcast (R6 pattern) ------------------
    if (t == 0) sh_ep1 = (unsigned)(ldv64(&g_done) >> 6) + 1u;
    const float my_r  = __ldg(&risk[i]);
    const float my_t  = __ldg(&time[i]);
    const float my_ev = __ldg(&event[i]);
    const float my_e  = expf(my_r);
    const int   b     = bucket_of(my_t);
    __syncthreads();
    const unsigned ep1 = sh_ep1;
    const int par = (int)(ep1 & 1u);

    // ---- Phase 1: histogram + slot scatter (plain stores, R6-proven) ------
    g_bsum[par ^ 1][i] = 0.0f;                   // prep next epoch
    g_cnt[par ^ 1][i]  = 0u;
    atomicAdd(&g_bsum[par][b], my_e);            // exact bucket sum
    unsigned c = atomicAdd(&g_cnt[par][b], 1u);
    if (c < CAP) g_slot[b * CAP + c] = make_float4(my_t, my_e, my_ev, 0.0f);
    gbar();  // B1

    // ---- Phase 2: owner of bucket i ---------------------------------------
    const float    bs  = ldvf(&g_bsum[par][i]);  // histogram (exact, even on overflow)
    const unsigned cnt = ldv32(&g_cnt[par][i]);
    float4 sl[CAP];
    #pragma unroll
    for (int m = 0; m < EAGER; m++) sl[m] = __ldcg(&g_slot[i * CAP + m]);
    const bool ok  = (cnt <= CAP);
    const int  len = (cnt < CAP) ? (int)cnt : CAP;
    for (int m = EAGER; m < len; m++) sl[m] = __ldcg(&g_slot[i * CAP + m]);

    // ---- In-block inclusive suffix scan via shuffles (1 sync) -------------
    const int lane = t & 31, w = t >> 5;
    float v = bs;
    #pragma unroll
    for (int d = 1; d < 32; d <<= 1) {
        float o = __shfl_down_sync(0xffffffffu, v, d);
        if (lane + d < 32) v += o;
    }
    if (lane == 0) s_w[w] = v;                   // warp total
    __syncthreads();
    float hiW = 0.0f, chunkTot = 0.0f;
    #pragma unroll
    for (int k = 0; k < 8; k++) {
        float wt = s_w[k];
        chunkTot += wt;
        if (k > w) hiW += wt;
    }
    const float excl = (v + hiW) - bs;           // exclusive suffix within chunk
    if (t == 0) g_chunk[blk] = chunkTot;
    gbar();  // B2 (fences cover the g_chunk store)

    // ---- Cross-chunk base: plain post-barrier reads (R6 pattern) ----------
    float hi = 0.0f;
    if (t < NBLK && t > blk) hi = ldvf(&g_chunk[t]);
    if (t < 64) {
        #pragma unroll
        for (int o = 16; o > 0; o >>= 1) hi += __shfl_down_sync(0xffffffffu, hi, o);
        if ((t & 31) == 0) s_hi[t >> 5] = hi;
    }
    __syncthreads();
    const float sb = s_hi[0] + s_hi[1] + excl;   // sum over buckets strictly > i

    // ---- Phase 3: per-element loss for my bucket (exact in-bucket ties) ---
    float num = 0.0f, den = 0.0f;
    if (ok) {
        for (int a = 0; a < len; a++) {
            float ev = sl[a].z;
            if (ev != 0.0f) {
                float s = sb;
                for (int m = 0; m < len; m++)
                    if (sl[m].x >= sl[a].x) s += sl[m].y;   // includes self
                num += ev * logf(sl[a].y / s);   // = ev*(theta - log s)
                den += ev;
            }
        }
    } else {  // exact fallback (P ~ 1e-6): rescan inputs for this bucket
        for (int j = 0; j < NELEM; j++) {
            float tj = __ldg(&time[j]);
            if (bucket_of(tj) == i && __ldg(&event[j]) != 0.0f) {
                float s = sb;
                for (int m2 = 0; m2 < NELEM; m2++) {
                    float tm = __ldg(&time[m2]);
                    if (bucket_of(tm) == i && tm >= tj) s += expf(__ldg(&risk[m2]));
                }
                num += __ldg(&risk[j]) - logf(s);
                den += 1.0f;
            }
        }
    }

    // ---- Block reduce -> ticket finalize (R6 verbatim) --------------------
    #pragma unroll
    for (int o = 16; o > 0; o >>= 1) {
        num += __shfl_down_sync(0xffffffffu, num, o);
        den += __shfl_down_sync(0xffffffffu, den, o);
    }
    if (lane == 0) { rn[w] = num; rd[w] = den; }
    __syncthreads();
    if (t == 0) {
        float n = 0.0f, d = 0.0f;
        #pragma unroll
        for (int k = 0; k < 8; k++) { n += rn[k]; d += rd[k]; }
        g_bpart[blk] = make_float2(n, d);
        __threadfence();
        ull old = atomicAdd(&g_done, 1ULL);
        if (old == ((ull)ep1 << 6) - 1ULL) {     // last arriver finalizes
            __threadfence();
            float tn = 0.0f, td = 0.0f;
            #pragma unroll 8
            for (int cb = 0; cb < NBLK; cb++) {
                float2 p = __ldcg(&g_bpart[cb]);
                tn += p.x; td += p.y;
            }
            out[0] = -tn / td;
        }
    }
}

extern "C" void kernel_launch(void* const* d_in, const int* in_sizes, int n_in,
                              void* d_out, int out_size) {
    const float* risk  = (const float*)d_in[0];
    const float* time  = (const float*)d_in[1];
    const float* event = (const float*)d_in[2];
    float* out = (float*)d_out;
    cox_kernel<<<NBLK, NTHR>>>(risk, time, event, out);
}